// round 13
// baseline (speedup 1.0000x reference)
#include <cuda_runtime.h>
#include <cstdint>

// ChannelDropout, single fused kernel, NO barrier / NO smem:
//   out[i] = sig[i] * scale[i / 750]
//   scale[ch] = kept(ch) / (eps + mean_j(||pos[ch]-mc[j]|| > 0.2))
//
// Each warp is self-sufficient: after batch-issuing its 8 LDG.128s, its four
// 8-lane sub-groups each compute one of the <=4 channel scales the tile
// touches (hidden under DRAM latency), reduce with 3 shfl_xor, and per-element
// scales are fetched with shfl.idx. Warps never wait on each other.
//
// Shapes: B=64, C=273, T=3000.  T/4 = 750 float4 per channel.

#define CD_TVEC   750                  // float4 per channel
#define CD_NMC    100
#define CD_DROP   0.2f
#define CD_EPS    1e-8f
#define CD_VPT    8                    // float4 per thread
#define CD_BLK    256
#define CD_TILE   (CD_BLK * CD_VPT)    // 2048 float4 per block (spans <=4 ch)

__global__ __launch_bounds__(CD_BLK)
void cd_fused_kernel(const float4* __restrict__ sig,
                     const float2* __restrict__ pos,
                     const float*  __restrict__ center,
                     const float2* __restrict__ mc,
                     float4* __restrict__ out,
                     int total_vec, int BC)
{
    const int tile0 = blockIdx.x * CD_TILE;
    const int base  = tile0 + threadIdx.x;
    const bool full = (tile0 + CD_TILE <= total_vec);

    // ---- 1) batch-issue the 8 sig loads (front-loaded MLP) ----
    float4 v[CD_VPT];
    if (full) {
#pragma unroll
        for (int j = 0; j < CD_VPT; j++)
            v[j] = __ldcs(&sig[base + j * CD_BLK]);
    } else {
#pragma unroll
        for (int j = 0; j < CD_VPT; j++)
            if (base + j * CD_BLK < total_vec)
                v[j] = __ldcs(&sig[base + j * CD_BLK]);
    }

    // ---- 2) warp-local scales: 8-lane group g owns channel first_ch+g ----
    const int lane     = threadIdx.x & 31;
    const int group    = lane >> 3;          // 0..3
    const int sub      = lane & 7;           // 0..7
    const int first_ch = tile0 / CD_TVEC;

    int ch = first_ch + group;
    ch = (ch < BC) ? ch : (BC - 1);          // clamp: keep warp converged

    const float2 p  = pos[ch];
    const float  px = p.x, py = p.y;

    // kept: distance from ban center (no FMA contraction -> match jax fp32)
    const float dx = px - center[0];
    const float dy = py - center[1];
    const float d2 = __fadd_rn(__fmul_rn(dx, dx), __fmul_rn(dy, dy));
    const float kept = (sqrtf(d2) > CD_DROP) ? 1.0f : 0.0f;

    // Monte-Carlo: 8 lanes split the 100 trials (12-13 each)
    int cnt = 0;
    for (int t = sub; t < CD_NMC; t += 8) {
        const float2 m   = mc[t];
        const float  ddx = px - m.x;
        const float  ddy = py - m.y;
        const float  dd2 = __fadd_rn(__fmul_rn(ddx, ddx),
                                     __fmul_rn(ddy, ddy));
        cnt += (sqrtf(dd2) > CD_DROP) ? 1 : 0;
    }
    // reduce within the 8-lane group (xor 1,2,4 stays inside the group)
    cnt += __shfl_xor_sync(0xffffffffu, cnt, 1);
    cnt += __shfl_xor_sync(0xffffffffu, cnt, 2);
    cnt += __shfl_xor_sync(0xffffffffu, cnt, 4);

    const float proba = (float)cnt / (float)CD_NMC;
    const float scale = kept / (CD_EPS + proba);   // valid on all lanes of group

    // ---- 3) per-element scale via shfl.idx from lane c*8, multiply, store ----
    if (full) {
        float s[CD_VPT];
#pragma unroll
        for (int j = 0; j < CD_VPT; j++) {
            const int c = (int)((unsigned)(base + j * CD_BLK) / CD_TVEC) - first_ch;
            s[j] = __shfl_sync(0xffffffffu, scale, c << 3);
        }
#pragma unroll
        for (int j = 0; j < CD_VPT; j++) {
            float4 r;
            r.x = v[j].x * s[j];
            r.y = v[j].y * s[j];
            r.z = v[j].z * s[j];
            r.w = v[j].w * s[j];
            __stcs(&out[base + j * CD_BLK], r);
        }
    } else {
#pragma unroll
        for (int j = 0; j < CD_VPT; j++) {
            const int idx   = base + j * CD_BLK;
            const int idx_c = (idx < total_vec) ? idx : (total_vec - 1);
            const int c     = (int)((unsigned)idx_c / CD_TVEC) - first_ch;
            const float sj  = __shfl_sync(0xffffffffu, scale, c << 3);
            if (idx < total_vec) {
                float4 r;
                r.x = v[j].x * sj;
                r.y = v[j].y * sj;
                r.z = v[j].z * sj;
                r.w = v[j].w * sj;
                __stcs(&out[idx], r);
            }
        }
    }
}

extern "C" void kernel_launch(void* const* d_in, const int* in_sizes, int n_in,
                              void* d_out, int out_size)
{
    const float4* sig    = (const float4*)d_in[0];   // brain_sig  (B,C,T) fp32
    const float2* pos    = (const float2*)d_in[1];   // positions  (B,C,2)
    const float*  center = (const float*) d_in[2];   // center     (2,)
    const float2* mc     = (const float2*)d_in[3];   // mc_centers (100,2)
    float4*       out    = (float4*)d_out;

    const int BC        = in_sizes[1] / 2;           // 17472
    const int total_vec = in_sizes[0] / 4;           // 13,104,000

    const int nblocks = (total_vec + CD_TILE - 1) / CD_TILE;  // 6399
    cd_fused_kernel<<<nblocks, CD_BLK>>>(sig, pos, center, mc, out,
                                         total_vec, BC);
}